// round 6
// baseline (speedup 1.0000x reference)
#include <cuda_runtime.h>

// Problem constants
#define NB   64
#define NC   256
#define NH   64
#define NW   64
#define NHW  4096                 // H*W
#define NPB  (NC*NHW)             // 1048576 elements per batch
#define KTOP 8
#define OUTC (NC+3)               // 259

// Scan config
#define PARTS 16                  // partitions per batch -> 1024 blocks
#define TPB   256
#define V4T   64                  // float4 loads per thread: (NPB/PARTS)/(4*TPB)
#define CAP   4096                // candidate buffer capacity per batch

__device__ unsigned long long g_cand[NB * CAP];
__device__ int                g_cnt[NB];   // zero at module load; reset by fx_final_kernel

__device__ __forceinline__ unsigned vmax3(unsigned a, unsigned b, unsigned c) {
#if defined(__CUDA_ARCH__) && __CUDA_ARCH__ >= 900
    return __vimax3_u32(a, b, c);
#else
    unsigned m = a > b ? a : b; return m > c ? m : c;
#endif
}

// Kernel A: threshold pre-pass + filtered candidate scan.
__global__ void __launch_bounds__(TPB) fx_scan_kernel(const float4* __restrict__ x) {
    const int part  = blockIdx.x;
    const int batch = blockIdx.y;
    const int t     = threadIdx.x;
    const float4* p = x + (size_t)batch * (NPB/4) + (size_t)part * (TPB * V4T) + t;

    __shared__ unsigned s_wmax[TPB/32];
    __shared__ unsigned s_L;

    // ---- warm-up: max over this thread's first 32 elements ----
    unsigned wm = 0u;
    #pragma unroll
    for (int i = 0; i < 8; ++i) {
        float4 v = p[i*TPB];
        unsigned m = vmax3(__float_as_uint(v.x), __float_as_uint(v.y), __float_as_uint(v.z));
        m = max(m, __float_as_uint(v.w));
        wm = max(wm, m);
    }
    #pragma unroll
    for (int off = 16; off > 0; off >>= 1)
        wm = max(wm, __shfl_xor_sync(0xffffffffu, wm, off));
    if ((t & 31) == 0) s_wmax[t >> 5] = wm;
    __syncthreads();
    if (t == 0) {
        unsigned L = s_wmax[0];
        #pragma unroll
        for (int w = 1; w < TPB/32; ++w) L = min(L, s_wmax[w]);
        // L = min of 8 warp-maxes => valid lower bound on block's 8th-largest.
        s_L = (L == 0u) ? 0u : (L - 1u);   // filter with strict > th  <=>  >= L
    }
    __syncthreads();
    const unsigned th = s_L;

    const unsigned idx0 = (unsigned)part * (NPB/PARTS) + (unsigned)t * 4u;
    int* cnt = &g_cnt[batch];
    unsigned long long* cand = &g_cand[(size_t)batch * CAP];

    // ---- main filtered scan: 16-element chunks ----
    #pragma unroll 4
    for (int i = 0; i < V4T; i += 4) {
        float4 v0 = p[(i+0)*TPB];
        float4 v1 = p[(i+1)*TPB];
        float4 v2 = p[(i+2)*TPB];
        float4 v3 = p[(i+3)*TPB];
        unsigned a0=__float_as_uint(v0.x), a1=__float_as_uint(v0.y), a2=__float_as_uint(v0.z), a3=__float_as_uint(v0.w);
        unsigned b0=__float_as_uint(v1.x), b1=__float_as_uint(v1.y), b2=__float_as_uint(v1.z), b3=__float_as_uint(v1.w);
        unsigned c0=__float_as_uint(v2.x), c1=__float_as_uint(v2.y), c2=__float_as_uint(v2.z), c3=__float_as_uint(v2.w);
        unsigned d0=__float_as_uint(v3.x), d1=__float_as_uint(v3.y), d2=__float_as_uint(v3.z), d3=__float_as_uint(v3.w);
        unsigned m;
        m = vmax3(a0, a1, a2);
        m = vmax3(m,  a3, b0);
        m = vmax3(m,  b1, b2);
        m = vmax3(m,  b3, c0);
        m = vmax3(m,  c1, c2);
        m = vmax3(m,  c3, d0);
        m = vmax3(m,  d1, d2);
        m = max(m, d3);
        if (m > th) {
            const unsigned base = idx0 + (unsigned)i * (TPB*4);
            unsigned va[16] = {a0,a1,a2,a3, b0,b1,b2,b3, c0,c1,c2,c3, d0,d1,d2,d3};
            #pragma unroll
            for (int j = 0; j < 16; ++j) {
                if (va[j] > th) {
                    unsigned idx = base + (unsigned)(j >> 2) * (TPB*4) + (unsigned)(j & 3);
                    unsigned long long key =
                        ((unsigned long long)va[j] << 32) | (unsigned)(~idx);
                    int pos = atomicAdd(cnt, 1);
                    if (pos < CAP) cand[pos] = key;
                }
            }
        }
    }
}

// Kernel B: per-batch top-8 selection over candidates + output write.
// Also resets g_cnt[batch] to 0 for the next graph replay.
__global__ void __launch_bounds__(256) fx_final_kernel(const float* __restrict__ x,
                                                       float* __restrict__ out) {
    const int batch = blockIdx.x;
    const int t     = threadIdx.x;
    const int lane  = t & 31;
    const int warp  = t >> 5;

    __shared__ unsigned long long s_win[KTOP];
    __shared__ unsigned long long s_red[256/32];

    float* ob = out + (size_t)batch * KTOP * OUTC;
    for (int i = t; i < KTOP*OUTC; i += 256) ob[i] = 0.0f;

    const int cnt = g_cnt[batch];
    unsigned long long loc[16];

    if (cnt <= CAP) {
        const unsigned long long* cand = &g_cand[(size_t)batch * CAP];
        #pragma unroll
        for (int j = 0; j < 16; ++j) {
            int pidx = t + j*256;
            loc[j] = (pidx < cnt) ? cand[pidx] : 0ull;
        }
    } else {
        // Fallback (statistically unreachable): full rescan, per-thread sorted top-8.
        const float* xb = x + (size_t)batch * NPB;
        #pragma unroll
        for (int j = 0; j < 16; ++j) loc[j] = 0ull;
        for (int e = t; e < NPB; e += 256) {
            unsigned u = __float_as_uint(xb[e]);
            unsigned long long key = ((unsigned long long)u << 32) | (unsigned)(~(unsigned)e);
            if (key > loc[KTOP-1]) {
                loc[KTOP-1] = key;
                #pragma unroll
                for (int j = KTOP-1; j > 0; --j) {
                    unsigned long long hi = loc[j-1] > loc[j] ? loc[j-1] : loc[j];
                    unsigned long long lo = loc[j-1] > loc[j] ? loc[j]   : loc[j-1];
                    loc[j-1] = hi; loc[j] = lo;
                }
            }
        }
    }

    // Reset the counter for the next replay (every thread has already read cnt).
    __syncthreads();
    if (t == 0) g_cnt[batch] = 0;

    // 8 extraction rounds: block-wide argmax (keys are unique), then clear winner.
    for (int r = 0; r < KTOP; ++r) {
        unsigned long long m = loc[0];
        #pragma unroll
        for (int j = 1; j < 16; ++j) if (loc[j] > m) m = loc[j];
        #pragma unroll
        for (int off = 16; off > 0; off >>= 1) {
            unsigned long long o = __shfl_xor_sync(0xffffffffu, m, off);
            if (o > m) m = o;
        }
        if (lane == 0) s_red[warp] = m;
        __syncthreads();
        if (t == 0) {
            unsigned long long M = s_red[0];
            #pragma unroll
            for (int w = 1; w < 8; ++w) if (s_red[w] > M) M = s_red[w];
            s_win[r] = M;
        }
        __syncthreads();
        unsigned long long M = s_win[r];
        #pragma unroll
        for (int j = 0; j < 16; ++j) if (loc[j] == M) loc[j] = 0ull;
    }

    if (t < KTOP) {
        unsigned long long key = s_win[t];
        if (key != 0ull) {   // guard: null key would decode to an OOB fm index
            unsigned vbits = (unsigned)(key >> 32);
            unsigned idx   = ~((unsigned)key);
            unsigned fm    = idx >> 12;          // / (H*W)
            unsigned rem   = idx & (NHW - 1);
            unsigned yy    = rem >> 6;           // / W
            unsigned xx    = rem & (NW - 1);
            float* row = ob + t * OUTC;
            row[fm]     = 1.0f;
            row[NC]     = __uint_as_float(vbits);
            row[NC + 1] = (float)xx / (float)(NW - 1);
            row[NC + 2] = (float)yy / (float)(NH - 1);
        }
    }
}

extern "C" void kernel_launch(void* const* d_in, const int* in_sizes, int n_in,
                              void* d_out, int out_size) {
    const float* x = (const float*)d_in[0];
    float* out = (float*)d_out;

    dim3 grid(PARTS, NB);
    fx_scan_kernel<<<grid, TPB>>>((const float4*)x);
    fx_final_kernel<<<NB, 256>>>(x, out);
}

// round 8
// speedup vs baseline: 2.2323x; 2.2323x over previous
#include <cuda_runtime.h>

// Problem constants
#define NB   64
#define NC   256
#define NH   64
#define NW   64
#define NHW  4096                 // H*W
#define NPB  (NC*NHW)             // 1048576 elements per batch
#define KTOP 8
#define OUTC (NC+3)               // 259

// Scan config
#define PARTS 16                  // partitions per batch -> 1024 blocks
#define TPB   256
#define V4T   64                  // float4 loads per thread: (NPB/PARTS)/(4*TPB)
#define SEG   1024                // candidate slots per (batch,part) segment

__device__ unsigned long long g_cand[NB * PARTS * SEG];  // 8 MB
__device__ int                g_scnt[NB * PARTS];        // raw per-segment counts
                                                         // (rewritten by every scan launch)

__device__ __forceinline__ unsigned vmax3(unsigned a, unsigned b, unsigned c) {
#if defined(__CUDA_ARCH__) && __CUDA_ARCH__ >= 900
    return __vimax3_u32(a, b, c);
#else
    unsigned m = a > b ? a : b; return m > c ? m : c;
#endif
}

// Kernel A: threshold pre-pass + filtered candidate scan.
// No global atomics: candidates go to a per-block private segment via a
// shared-memory counter; the raw count is published at block end.
__global__ void __launch_bounds__(TPB) fx_scan_kernel(const float4* __restrict__ x) {
    const int part  = blockIdx.x;
    const int batch = blockIdx.y;
    const int t     = threadIdx.x;
    const float4* p = x + (size_t)batch * (NPB/4) + (size_t)part * (TPB * V4T) + t;

    __shared__ unsigned s_wmax[TPB/32];
    __shared__ unsigned s_L;
    __shared__ int      s_cnt;

    if (t == 0) s_cnt = 0;

    // ---- warm-up: max over this thread's first 32 elements ----
    unsigned wm = 0u;
    #pragma unroll
    for (int i = 0; i < 8; ++i) {
        float4 v = p[i*TPB];
        unsigned m = vmax3(__float_as_uint(v.x), __float_as_uint(v.y), __float_as_uint(v.z));
        m = max(m, __float_as_uint(v.w));
        wm = max(wm, m);
    }
    #pragma unroll
    for (int off = 16; off > 0; off >>= 1)
        wm = max(wm, __shfl_xor_sync(0xffffffffu, wm, off));
    if ((t & 31) == 0) s_wmax[t >> 5] = wm;
    __syncthreads();
    if (t == 0) {
        unsigned L = s_wmax[0];
        #pragma unroll
        for (int w = 1; w < TPB/32; ++w) L = min(L, s_wmax[w]);
        // L = min of 8 warp-maxes => valid lower bound on block's 8th-largest.
        s_L = (L == 0u) ? 0u : (L - 1u);   // filter with strict > th  <=>  >= L
    }
    __syncthreads();
    const unsigned th = s_L;

    const unsigned idx0 = (unsigned)part * (NPB/PARTS) + (unsigned)t * 4u;
    unsigned long long* seg = &g_cand[(size_t)(batch * PARTS + part) * SEG];

    // ---- main filtered scan: 16-element chunks ----
    #pragma unroll 4
    for (int i = 0; i < V4T; i += 4) {
        float4 v0 = p[(i+0)*TPB];
        float4 v1 = p[(i+1)*TPB];
        float4 v2 = p[(i+2)*TPB];
        float4 v3 = p[(i+3)*TPB];
        unsigned a0=__float_as_uint(v0.x), a1=__float_as_uint(v0.y), a2=__float_as_uint(v0.z), a3=__float_as_uint(v0.w);
        unsigned b0=__float_as_uint(v1.x), b1=__float_as_uint(v1.y), b2=__float_as_uint(v1.z), b3=__float_as_uint(v1.w);
        unsigned c0=__float_as_uint(v2.x), c1=__float_as_uint(v2.y), c2=__float_as_uint(v2.z), c3=__float_as_uint(v2.w);
        unsigned d0=__float_as_uint(v3.x), d1=__float_as_uint(v3.y), d2=__float_as_uint(v3.z), d3=__float_as_uint(v3.w);
        unsigned m;
        m = vmax3(a0, a1, a2);
        m = vmax3(m,  a3, b0);
        m = vmax3(m,  b1, b2);
        m = vmax3(m,  b3, c0);
        m = vmax3(m,  c1, c2);
        m = vmax3(m,  c3, d0);
        m = vmax3(m,  d1, d2);
        m = max(m, d3);
        if (m > th) {
            const unsigned base = idx0 + (unsigned)i * (TPB*4);
            unsigned va[16] = {a0,a1,a2,a3, b0,b1,b2,b3, c0,c1,c2,c3, d0,d1,d2,d3};
            #pragma unroll
            for (int j = 0; j < 16; ++j) {
                if (va[j] > th) {
                    unsigned idx = base + (unsigned)(j >> 2) * (TPB*4) + (unsigned)(j & 3);
                    unsigned long long key =
                        ((unsigned long long)va[j] << 32) | (unsigned)(~idx);
                    int pos = atomicAdd(&s_cnt, 1);      // shared-memory atomic only
                    if (pos < SEG) seg[pos] = key;
                }
            }
        }
    }

    __syncthreads();
    if (t == 0) g_scnt[batch * PARTS + part] = s_cnt;   // raw count (may exceed SEG)
}

// Kernel B: per-batch top-8 over candidate segments + output write.
__global__ void __launch_bounds__(256) fx_final_kernel(const float* __restrict__ x,
                                                       float* __restrict__ out) {
    const int batch = blockIdx.x;
    const int t     = threadIdx.x;
    const int lane  = t & 31;
    const int warp  = t >> 5;

    __shared__ unsigned long long s_win[KTOP];
    __shared__ unsigned long long s_red[256/32];

    float* ob = out + (size_t)batch * KTOP * OUTC;
    for (int i = t; i < KTOP*OUTC; i += 256) ob[i] = 0.0f;

    // Prefetch all segment counts (broadcast loads).
    int cnts[PARTS];
    bool ovf = false;
    #pragma unroll
    for (int s = 0; s < PARTS; ++s) {
        cnts[s] = g_scnt[batch * PARTS + s];
        if (cnts[s] > SEG) ovf = true;
    }

    // Per-thread sorted top-8 (descending), robust to any candidate count.
    unsigned long long loc[KTOP];
    #pragma unroll
    for (int j = 0; j < KTOP; ++j) loc[j] = 0ull;

    if (!ovf) {
        #pragma unroll
        for (int s = 0; s < PARTS; ++s) {
            const unsigned long long* seg = &g_cand[(size_t)(batch * PARTS + s) * SEG];
            const int c = cnts[s];
            for (int i = t; i < c; i += 256) {
                unsigned long long key = seg[i];
                if (key > loc[KTOP-1]) {
                    loc[KTOP-1] = key;
                    #pragma unroll
                    for (int j = KTOP-1; j > 0; --j) {
                        unsigned long long hi = loc[j-1] > loc[j] ? loc[j-1] : loc[j];
                        unsigned long long lo = loc[j-1] > loc[j] ? loc[j]   : loc[j-1];
                        loc[j-1] = hi; loc[j] = lo;
                    }
                }
            }
        }
    } else {
        // Fallback (rare): exact full rescan.
        const float* xb = x + (size_t)batch * NPB;
        for (int e = t; e < NPB; e += 256) {
            unsigned u = __float_as_uint(xb[e]);
            unsigned long long key = ((unsigned long long)u << 32) | (unsigned)(~(unsigned)e);
            if (key > loc[KTOP-1]) {
                loc[KTOP-1] = key;
                #pragma unroll
                for (int j = KTOP-1; j > 0; --j) {
                    unsigned long long hi = loc[j-1] > loc[j] ? loc[j-1] : loc[j];
                    unsigned long long lo = loc[j-1] > loc[j] ? loc[j]   : loc[j-1];
                    loc[j-1] = hi; loc[j] = lo;
                }
            }
        }
    }

    // 8 extraction rounds: block-wide argmax (keys unique), then clear winner.
    for (int r = 0; r < KTOP; ++r) {
        unsigned long long m = loc[0];
        #pragma unroll
        for (int j = 1; j < KTOP; ++j) if (loc[j] > m) m = loc[j];
        #pragma unroll
        for (int off = 16; off > 0; off >>= 1) {
            unsigned long long o = __shfl_xor_sync(0xffffffffu, m, off);
            if (o > m) m = o;
        }
        if (lane == 0) s_red[warp] = m;
        __syncthreads();
        if (t == 0) {
            unsigned long long M = s_red[0];
            #pragma unroll
            for (int w = 1; w < 8; ++w) if (s_red[w] > M) M = s_red[w];
            s_win[r] = M;
        }
        __syncthreads();
        unsigned long long M = s_win[r];
        #pragma unroll
        for (int j = 0; j < KTOP; ++j) if (loc[j] == M) loc[j] = 0ull;
    }

    if (t < KTOP) {
        unsigned long long key = s_win[t];
        if (key != 0ull) {   // guard: null key would decode to an OOB fm index
            unsigned vbits = (unsigned)(key >> 32);
            unsigned idx   = ~((unsigned)key);
            unsigned fm    = idx >> 12;          // / (H*W)
            unsigned rem   = idx & (NHW - 1);
            unsigned yy    = rem >> 6;           // / W
            unsigned xx    = rem & (NW - 1);
            float* row = ob + t * OUTC;
            row[fm]     = 1.0f;
            row[NC]     = __uint_as_float(vbits);
            row[NC + 1] = (float)xx / (float)(NW - 1);
            row[NC + 2] = (float)yy / (float)(NH - 1);
        }
    }
}

extern "C" void kernel_launch(void* const* d_in, const int* in_sizes, int n_in,
                              void* d_out, int out_size) {
    const float* x = (const float*)d_in[0];
    float* out = (float*)d_out;

    dim3 grid(PARTS, NB);
    fx_scan_kernel<<<grid, TPB>>>((const float4*)x);
    fx_final_kernel<<<NB, 256>>>(x, out);
}

// round 11
// speedup vs baseline: 2.2540x; 1.0098x over previous
#include <cuda_runtime.h>

// Problem constants
#define NB   64
#define NC   256
#define NH   64
#define NW   64
#define NHW  4096                 // H*W
#define NPB  (NC*NHW)             // 1048576 elements per batch
#define KTOP 8
#define OUTC (NC+3)               // 259

// Scan config
#define PARTS 16                  // partitions per batch -> 1024 blocks
#define TPB   256
#define V4T   64                  // float4 loads per thread: (NPB/PARTS)/(4*TPB)
#define SEG   1024                // candidate slots per (batch,part) segment

__device__ unsigned long long g_cand[NB * PARTS * SEG];  // 8 MB
__device__ int                g_scnt[NB * PARTS];        // raw per-segment counts
                                                         // (rewritten by every scan launch)

__device__ __forceinline__ unsigned vmax3(unsigned a, unsigned b, unsigned c) {
#if defined(__CUDA_ARCH__) && __CUDA_ARCH__ >= 900
    return __vimax3_u32(a, b, c);
#else
    unsigned m = a > b ? a : b; return m > c ? m : c;
#endif
}

// Kernel A: threshold pre-pass + filtered candidate scan.
// No global atomics: candidates go to a per-block private segment via a
// shared-memory counter; the raw count is published at block end.
__global__ void __launch_bounds__(TPB) fx_scan_kernel(const float4* __restrict__ x) {
    const int part  = blockIdx.x;
    const int batch = blockIdx.y;
    const int t     = threadIdx.x;
    const float4* p = x + (size_t)batch * (NPB/4) + (size_t)part * (TPB * V4T) + t;

    __shared__ unsigned s_wmax[TPB/32];
    __shared__ unsigned s_L;
    __shared__ int      s_cnt;

    if (t == 0) s_cnt = 0;

    // ---- warm-up: max over this thread's first 32 elements ----
    unsigned wm = 0u;
    #pragma unroll
    for (int i = 0; i < 8; ++i) {
        float4 v = p[i*TPB];
        unsigned m = vmax3(__float_as_uint(v.x), __float_as_uint(v.y), __float_as_uint(v.z));
        m = max(m, __float_as_uint(v.w));
        wm = max(wm, m);
    }
    #pragma unroll
    for (int off = 16; off > 0; off >>= 1)
        wm = max(wm, __shfl_xor_sync(0xffffffffu, wm, off));
    if ((t & 31) == 0) s_wmax[t >> 5] = wm;
    __syncthreads();
    if (t == 0) {
        unsigned L = s_wmax[0];
        #pragma unroll
        for (int w = 1; w < TPB/32; ++w) L = min(L, s_wmax[w]);
        // L = min of 8 warp-maxes => valid lower bound on block's 8th-largest.
        s_L = (L == 0u) ? 0u : (L - 1u);   // filter with strict > th  <=>  >= L
    }
    __syncthreads();
    const unsigned th = s_L;

    const unsigned idx0 = (unsigned)part * (NPB/PARTS) + (unsigned)t * 4u;
    unsigned long long* seg = &g_cand[(size_t)(batch * PARTS + part) * SEG];

    // ---- main filtered scan: 16-element chunks ----
    #pragma unroll 4
    for (int i = 0; i < V4T; i += 4) {
        float4 v0 = p[(i+0)*TPB];
        float4 v1 = p[(i+1)*TPB];
        float4 v2 = p[(i+2)*TPB];
        float4 v3 = p[(i+3)*TPB];
        unsigned a0=__float_as_uint(v0.x), a1=__float_as_uint(v0.y), a2=__float_as_uint(v0.z), a3=__float_as_uint(v0.w);
        unsigned b0=__float_as_uint(v1.x), b1=__float_as_uint(v1.y), b2=__float_as_uint(v1.z), b3=__float_as_uint(v1.w);
        unsigned c0=__float_as_uint(v2.x), c1=__float_as_uint(v2.y), c2=__float_as_uint(v2.z), c3=__float_as_uint(v2.w);
        unsigned d0=__float_as_uint(v3.x), d1=__float_as_uint(v3.y), d2=__float_as_uint(v3.z), d3=__float_as_uint(v3.w);
        unsigned m;
        m = vmax3(a0, a1, a2);
        m = vmax3(m,  a3, b0);
        m = vmax3(m,  b1, b2);
        m = vmax3(m,  b3, c0);
        m = vmax3(m,  c1, c2);
        m = vmax3(m,  c3, d0);
        m = vmax3(m,  d1, d2);
        m = max(m, d3);
        if (m > th) {
            const unsigned base = idx0 + (unsigned)i * (TPB*4);
            unsigned va[16] = {a0,a1,a2,a3, b0,b1,b2,b3, c0,c1,c2,c3, d0,d1,d2,d3};
            #pragma unroll
            for (int j = 0; j < 16; ++j) {
                if (va[j] > th) {
                    unsigned idx = base + (unsigned)(j >> 2) * (TPB*4) + (unsigned)(j & 3);
                    unsigned long long key =
                        ((unsigned long long)va[j] << 32) | (unsigned)(~idx);
                    int pos = atomicAdd(&s_cnt, 1);      // shared-memory atomic only
                    if (pos < SEG) seg[pos] = key;
                }
            }
        }
    }

    __syncthreads();
    if (t == 0) g_scnt[batch * PARTS + part] = s_cnt;   // raw count (may exceed SEG)
}

// Kernel B: per-batch top-8 over candidate segments + output write.
// Flat fully-unrolled predicated sweep over all PARTS*SEG slots -> high MLP.
__global__ void __launch_bounds__(256) fx_final_kernel(const float* __restrict__ x,
                                                       float* __restrict__ out) {
    const int batch = blockIdx.x;
    const int t     = threadIdx.x;
    const int lane  = t & 31;
    const int warp  = t >> 5;

    __shared__ unsigned long long s_win[KTOP];
    __shared__ unsigned long long s_red[256/32];

    float* ob = out + (size_t)batch * KTOP * OUTC;
    for (int i = t; i < KTOP*OUTC; i += 256) ob[i] = 0.0f;

    // Prefetch all segment counts (broadcast loads, constant-indexed register array).
    int cnts[PARTS];
    bool ovf = false;
    #pragma unroll
    for (int s = 0; s < PARTS; ++s) {
        cnts[s] = g_scnt[batch * PARTS + s];
        if (cnts[s] > SEG) ovf = true;
    }

    // Per-thread sorted top-8 (descending), robust to any candidate count.
    unsigned long long loc[KTOP];
    #pragma unroll
    for (int j = 0; j < KTOP; ++j) loc[j] = 0ull;

    if (!ovf) {
        const unsigned long long* base = &g_cand[(size_t)batch * PARTS * SEG];
        // 64 independent predicated loads per thread; inserts are rare.
        #pragma unroll
        for (int s = 0; s < PARTS; ++s) {
            #pragma unroll
            for (int j = 0; j < SEG/256; ++j) {      // 4 per segment
                const int k = t + j * 256;
                unsigned long long key = (k < cnts[s]) ? base[s * SEG + k] : 0ull;
                if (key > loc[KTOP-1]) {
                    loc[KTOP-1] = key;
                    #pragma unroll
                    for (int q = KTOP-1; q > 0; --q) {
                        unsigned long long hi = loc[q-1] > loc[q] ? loc[q-1] : loc[q];
                        unsigned long long lo = loc[q-1] > loc[q] ? loc[q]   : loc[q-1];
                        loc[q-1] = hi; loc[q] = lo;
                    }
                }
            }
        }
    } else {
        // Fallback (rare): exact full rescan.
        const float* xb = x + (size_t)batch * NPB;
        for (int e = t; e < NPB; e += 256) {
            unsigned u = __float_as_uint(xb[e]);
            unsigned long long key = ((unsigned long long)u << 32) | (unsigned)(~(unsigned)e);
            if (key > loc[KTOP-1]) {
                loc[KTOP-1] = key;
                #pragma unroll
                for (int q = KTOP-1; q > 0; --q) {
                    unsigned long long hi = loc[q-1] > loc[q] ? loc[q-1] : loc[q];
                    unsigned long long lo = loc[q-1] > loc[q] ? loc[q]   : loc[q-1];
                    loc[q-1] = hi; loc[q] = lo;
                }
            }
        }
    }

    // 8 extraction rounds: block-wide argmax (keys unique), then clear winner.
    for (int r = 0; r < KTOP; ++r) {
        unsigned long long m = loc[0];
        #pragma unroll
        for (int j = 1; j < KTOP; ++j) if (loc[j] > m) m = loc[j];
        #pragma unroll
        for (int off = 16; off > 0; off >>= 1) {
            unsigned long long o = __shfl_xor_sync(0xffffffffu, m, off);
            if (o > m) m = o;
        }
        if (lane == 0) s_red[warp] = m;
        __syncthreads();
        if (t == 0) {
            unsigned long long M = s_red[0];
            #pragma unroll
            for (int w = 1; w < 8; ++w) if (s_red[w] > M) M = s_red[w];
            s_win[r] = M;
        }
        __syncthreads();
        unsigned long long M = s_win[r];
        #pragma unroll
        for (int j = 0; j < KTOP; ++j) if (loc[j] == M) loc[j] = 0ull;
    }

    if (t < KTOP) {
        unsigned long long key = s_win[t];
        if (key != 0ull) {   // guard: null key would decode to an OOB fm index
            unsigned vbits = (unsigned)(key >> 32);
            unsigned idx   = ~((unsigned)key);
            unsigned fm    = idx >> 12;          // / (H*W)
            unsigned rem   = idx & (NHW - 1);
            unsigned yy    = rem >> 6;           // / W
            unsigned xx    = rem & (NW - 1);
            float* row = ob + t * OUTC;
            row[fm]     = 1.0f;
            row[NC]     = __uint_as_float(vbits);
            row[NC + 1] = (float)xx / (float)(NW - 1);
            row[NC + 2] = (float)yy / (float)(NH - 1);
        }
    }
}

extern "C" void kernel_launch(void* const* d_in, const int* in_sizes, int n_in,
                              void* d_out, int out_size) {
    const float* x = (const float*)d_in[0];
    float* out = (float*)d_out;

    dim3 grid(PARTS, NB);
    fx_scan_kernel<<<grid, TPB>>>((const float4*)x);
    fx_final_kernel<<<NB, 256>>>(x, out);
}